// round 6
// baseline (speedup 1.0000x reference)
#include <cuda_runtime.h>

#define B_ 64
#define T_ 800
#define J_ 50
#define D_ 200

constexpr int TPB1 = 256;
constexpr int NW   = 8;          // warps per block
constexpr int NP   = 4;          // warp pairs
constexpr int TP   = 8;          // t-rows per pair
constexpr int TBLK = NP * TP;    // 32 t-rows per block
constexpr int UPITCH4 = 51;      // float4 per u row (204 words; conflict-free)
constexpr int D4 = D_ / 4;       // 50
constexpr int KH = 25;           // d4-chunks per half
constexpr int NCHUNK = 25;       // = T_/TBLK
constexpr int XP = 52;           // X pitch (floats)

// scratch (no cudaMalloc allowed)
__device__ float2 g_cm[B_ * NCHUNK];            // (chunk max, chunk expsum)
__device__ float  g_part[B_ * NCHUNK * D_];     // unnormalized q2c partials
__device__ __align__(16) float g_q2c[B_ * D_];  // combined q2c

// ---- packed f32x2 helpers ----
__device__ __forceinline__ void fma2(unsigned long long& d, unsigned long long a, unsigned long long b) {
    asm("fma.rn.f32x2 %0, %1, %2, %0;" : "+l"(d) : "l"(a), "l"(b));
}
__device__ __forceinline__ float2 unpack2(unsigned long long v) {
    float2 r; asm("mov.b64 {%0, %1}, %2;" : "=f"(r.x), "=f"(r.y) : "l"(v)); return r;
}
__device__ __forceinline__ float warpSum(float v) {
    #pragma unroll
    for (int o = 16; o > 0; o >>= 1) v += __shfl_xor_sync(0xffffffffu, v, o);
    return v;
}
__device__ __forceinline__ float warpMax(float v) {
    #pragma unroll
    for (int o = 16; o > 0; o >>= 1) v = fmaxf(v, __shfl_xor_sync(0xffffffffu, v, o));
    return v;
}
__device__ __forceinline__ void barPair(int p) {
    asm volatile("bar.sync %0, 64;" :: "r"(p + 1) : "memory");
}

// =====================================================================
// K1: per (b, 32 t-rows). Warp pairs split the d-dimension: each warp
// streams only half the u tile through the smem crossbar.
// smem: u_s 40800 + hw_s 25600 + X 6656 + su 208 + m/es 256 = 73520 B
// =====================================================================
__global__ __launch_bounds__(TPB1, 3) void bidaf_k1(
    const float* __restrict__ h, const float* __restrict__ u,
    const float* __restrict__ w_h, const float* __restrict__ b_h,
    const float* __restrict__ w_u, const float* __restrict__ b_u,
    const float* __restrict__ w_hu, const float* __restrict__ b_hu,
    float* __restrict__ out)
{
    extern __shared__ char smem_raw[];
    float* u_s  = (float*)smem_raw;                  // 50*204
    float* hw_s = u_s + J_ * UPITCH4 * 4;            // 32*200
    float* x_s  = hw_s + TBLK * D_;                  // 32*52
    float* su_s = x_s + TBLK * XP;                   // 50 (+2 pad)
    float* m_s  = su_s + J_ + 2;                     // 32
    float* es_s = m_s + TBLK;                        // 32

    const int b    = blockIdx.y;
    const int c    = blockIdx.x;
    const int t0   = c * TBLK;
    const int tid  = threadIdx.x;
    const int warp = tid >> 5, lane = tid & 31;
    const int pair = warp >> 1, half = warp & 1;

    const float4* u4g = (const float4*)u;
    const float4* h4g = (const float4*)h;
    float4* us4 = (float4*)u_s;

    // ---- load u[b] tile into smem ----
    for (int idx = tid; idx < J_ * UPITCH4; idx += TPB1) {
        int j = idx / UPITCH4, k = idx - j * UPITCH4;
        if (k < D4) us4[j * UPITCH4 + k] = u4g[(b * J_ + j) * D4 + k];
    }
    const float bias = b_h[0] + b_u[0] + b_hu[0];
    __syncthreads();

    // ---- su_s[j] = dot(u_j, w_u) + bias ----
    const float4* wu4 = (const float4*)w_u;
    for (int j = warp; j < J_; j += NW) {
        float acc = 0.f;
        for (int k = lane; k < D4; k += 32) {
            float4 a = us4[j * UPITCH4 + k], w = wu4[k];
            acc += a.x * w.x + a.y * w.y + a.z * w.z + a.w * w.w;
        }
        acc = warpSum(acc);
        if (lane == 0) su_s[j] = acc + bias;
    }
    __syncthreads();

    // ---- phase A: hw = h * w_hu (to smem), sh = dot(h, w_h) ----
    // warp w owns block-rows [w*4, w*4+4)
    const float4* whu4 = (const float4*)w_hu;
    const float4* wh4  = (const float4*)w_h;
    float4* hw4 = (float4*)hw_s + warp * (4 * D4);
    const int tw = t0 + warp * 4;
    float sh[4];
    #pragma unroll
    for (int tt = 0; tt < 4; tt++) {
        long rb = (long)(b * T_ + tw + tt) * D4;
        float4 a = h4g[rb + lane];
        float4 w1 = whu4[lane];
        hw4[tt * D4 + lane] =
            make_float4(a.x * w1.x, a.y * w1.y, a.z * w1.z, a.w * w1.w);
        float4 w2 = wh4[lane];
        float p = a.x * w2.x + a.y * w2.y + a.z * w2.z + a.w * w2.w;
        if (lane < D4 - 32) {
            float4 a2 = h4g[rb + 32 + lane];
            float4 w1b = whu4[32 + lane];
            hw4[tt * D4 + 32 + lane] =
                make_float4(a2.x * w1b.x, a2.y * w1b.y, a2.z * w1b.z, a2.w * w1b.w);
            float4 w2b = wh4[32 + lane];
            p += a2.x * w2b.x + a2.y * w2b.y + a2.z * w2b.z + a2.w * w2b.w;
        }
        sh[tt] = warpSum(p);
    }
    barPair(pair);   // partner's hw rows must be visible

    // ---- phase B: s-partials over this warp's d-half, all 8 pair rows ----
    const bool jv = (lane < J_ - 32);
    unsigned long long acc[TP][2];
    #pragma unroll
    for (int r = 0; r < TP; r++) { acc[r][0] = 0ull; acc[r][1] = 0ull; }

    const ulonglong2* usU = (const ulonglong2*)u_s;
    const ulonglong2* hwP = (const ulonglong2*)hw_s + pair * (TP * D4);
    const int j0 = lane, j1 = lane + 32;
    const ulonglong2* uj0 = usU + j0 * UPITCH4 + half * KH;
    const ulonglong2* uj1 = usU + j1 * UPITCH4 + half * KH;
    const ulonglong2* hwH = hwP + half * KH;

    #pragma unroll 5
    for (int k = 0; k < KH; k++) {
        ulonglong2 U0 = uj0[k];
        ulonglong2 U1; U1.x = 0ull; U1.y = 0ull;
        if (jv) U1 = uj1[k];
        #pragma unroll
        for (int r = 0; r < TP; r++) {
            ulonglong2 Hb = hwH[r * D4 + k];   // broadcast
            fma2(acc[r][0], U0.x, Hb.x);
            fma2(acc[r][0], U0.y, Hb.y);
            fma2(acc[r][1], U1.x, Hb.x);
            fma2(acc[r][1], U1.y, Hb.y);
        }
    }

    // ---- write partner-row partials to X ----
    #pragma unroll
    for (int rr = 0; rr < 4; rr++) {
        int r = (1 - half) * 4 + rr;
        float2 p0 = unpack2(acc[r][0]);
        x_s[(pair * TP + r) * XP + j0] = p0.x + p0.y;
        if (jv) {
            float2 p1 = unpack2(acc[r][1]);
            x_s[(pair * TP + r) * XP + j1] = p1.x + p1.y;
        }
    }
    barPair(pair);

    // ---- softmax for own 4 rows; a2 overlays THIS pair's hw rows ----
    float2* a2p = (float2*)(hw_s + pair * (TP * D_));   // pair-local overlay
    const float su0 = su_s[j0];
    const float su1 = jv ? su_s[j1] : -1e30f;
    #pragma unroll
    for (int rr = 0; rr < 4; rr++) {
        int r = half * 4 + rr;
        float2 p0 = unpack2(acc[r][0]);
        float2 p1 = unpack2(acc[r][1]);
        float s0 = (p0.x + p0.y) + x_s[(pair * TP + r) * XP + j0] + sh[rr] + su0;
        float s1 = (p1.x + p1.y) + (jv ? x_s[(pair * TP + r) * XP + j1] : 0.f) + sh[rr] + su1;
        float mx = warpMax(fmaxf(s0, s1));
        float e0 = __expf(s0 - mx);
        float e1 = __expf(s1 - mx);
        float sm = warpSum(e0 + e1);
        float inv = 1.f / sm;
        float a0 = e0 * inv, a1 = e1 * inv;
        a2p[r * XP + j0] = make_float2(a0, a0);
        if (jv) a2p[r * XP + j1] = make_float2(a1, a1);
        if (lane == 0) m_s[pair * TP + r] = mx;
    }
    barPair(pair);

    // ---- c2q for this warp's d-half, all 8 pair rows ----
    unsigned long long cacc[TP][2];
    #pragma unroll
    for (int r = 0; r < TP; r++) { cacc[r][0] = 0ull; cacc[r][1] = 0ull; }

    const bool kvalid = (lane < KH);
    const int myk = half * KH + lane;
    const ulonglong2* ukp = usU + (kvalid ? myk : 0);
    #pragma unroll 2
    for (int j = 0; j < J_; j++) {
        ulonglong2 Ua; Ua.x = 0ull; Ua.y = 0ull;
        if (kvalid) Ua = ukp[j * UPITCH4];
        #pragma unroll
        for (int r = 0; r < TP; r++) {
            unsigned long long aj = *(const unsigned long long*)&a2p[r * XP + j]; // bcast
            fma2(cacc[r][0], aj, Ua.x);
            fma2(cacc[r][1], aj, Ua.y);
        }
    }

    // ---- epilogue: out[b,t, 0:200]=h, [200:400]=c2q, [400:600]=h*c2q ----
    if (kvalid) {
        #pragma unroll
        for (int r = 0; r < TP; r++) {
            int t = t0 + pair * TP + r;
            long rb = (long)(b * T_ + t) * D4;
            float4* o4 = (float4*)out + (long)(b * T_ + t) * (4 * D4);
            float4 ha = h4g[rb + myk];
            float2 ca = unpack2(cacc[r][0]);
            float2 cb = unpack2(cacc[r][1]);
            float4 c0 = make_float4(ca.x, ca.y, cb.x, cb.y);
            __stcs(o4 + myk, ha);
            __stcs(o4 + 50 + myk, c0);
            __stcs(o4 + 100 + myk,
                   make_float4(ha.x * c0.x, ha.y * c0.y, ha.z * c0.z, ha.w * c0.w));
        }
    }

    // ---- chunk-local q2c partial: m_c, s_c, sum_t exp(m_t-m_c)*h[t,:] ----
    __syncthreads();
    if (warp == 0) {
        float mv = (lane < TBLK) ? m_s[lane] : -3.0e38f;
        float mc = warpMax(mv);
        float ev = (lane < TBLK) ? __expf(mv - mc) : 0.f;
        float sc = warpSum(ev);
        if (lane < TBLK) es_s[lane] = ev;
        if (lane == 0) g_cm[b * NCHUNK + c] = make_float2(mc, sc);
    }
    __syncthreads();
    if (tid < D_) {
        const float* hp = h + ((long)b * T_ + t0) * D_ + tid;
        float a0 = 0.f, a1 = 0.f, a2 = 0.f, a3 = 0.f;
        #pragma unroll
        for (int t = 0; t < TBLK; t += 4) {
            a0 += es_s[t]     * hp[t * D_];
            a1 += es_s[t + 1] * hp[(t + 1) * D_];
            a2 += es_s[t + 2] * hp[(t + 2) * D_];
            a3 += es_s[t + 3] * hp[(t + 3) * D_];
        }
        g_part[(b * NCHUNK + c) * D_ + tid] = (a0 + a1) + (a2 + a3);
    }
}

// =====================================================================
// K2: per-batch combine of chunk records -> g_q2c[b,:]
// =====================================================================
__global__ __launch_bounds__(256) void bidaf_k2()
{
    __shared__ float ws[32];
    __shared__ float Ss;
    const int b = blockIdx.x, tid = threadIdx.x;
    if (tid < 32) {
        float2 cm = (tid < NCHUNK) ? g_cm[b * NCHUNK + tid] : make_float2(-3.0e38f, 0.f);
        float M = warpMax(cm.x);
        float e = (tid < NCHUNK) ? __expf(cm.x - M) : 0.f;
        float S = warpSum(e * cm.y);
        ws[tid] = e;
        if (tid == 0) Ss = S;
    }
    __syncthreads();
    if (tid < D_) {
        float acc = 0.f;
        #pragma unroll
        for (int c2 = 0; c2 < NCHUNK; c2++)
            acc += ws[c2] * g_part[(b * NCHUNK + c2) * D_ + tid];
        g_q2c[b * D_ + tid] = acc / Ss;
    }
}

// =====================================================================
// K3: pure streaming: out[b,t,600:800] = h[b,t,:] * q2c[b,:]
// =====================================================================
__global__ __launch_bounds__(256) void bidaf_k3(const float* __restrict__ h,
                                                float* __restrict__ out)
{
    __shared__ __align__(16) float qs[D_];
    const int b = blockIdx.y, tseg = blockIdx.x, tid = threadIdx.x;
    if (tid < D_) qs[tid] = g_q2c[b * D_ + tid];
    __syncthreads();

    const float4* q4 = (const float4*)qs;
    const int t0 = tseg * TBLK;
    #pragma unroll
    for (int r = 0; r < (TBLK * D4 + 255) / 256; r++) {
        int idx = r * 256 + tid;
        if (idx < TBLK * D4) {
            int t = idx / D4, d4 = idx - (idx / D4) * D4;
            long bt = (long)b * T_ + t0 + t;
            float4 hv = __ldg(((const float4*)h) + bt * D4 + d4);
            float4 q  = q4[d4];
            __stcs(((float4*)out) + bt * (4 * D4) + 150 + d4,
                   make_float4(hv.x * q.x, hv.y * q.y, hv.z * q.z, hv.w * q.w));
        }
    }
}

// =====================================================================
extern "C" void kernel_launch(void* const* d_in, const int* in_sizes, int n_in,
                              void* d_out, int out_size)
{
    const float* h    = (const float*)d_in[0];
    const float* u    = (const float*)d_in[1];
    const float* w_h  = (const float*)d_in[2];
    const float* b_h  = (const float*)d_in[3];
    const float* w_u  = (const float*)d_in[4];
    const float* b_u  = (const float*)d_in[5];
    const float* w_hu = (const float*)d_in[6];
    const float* b_hu = (const float*)d_in[7];
    float* out = (float*)d_out;

    constexpr int SMEM1 = (J_ * UPITCH4 * 4      // u_s
                         + TBLK * D_             // hw_s
                         + TBLK * XP             // x_s
                         + J_ + 2                // su_s
                         + 2 * TBLK) * 4;        // m_s + es_s
    cudaFuncSetAttribute(bidaf_k1, cudaFuncAttributeMaxDynamicSharedMemorySize, SMEM1);

    bidaf_k1<<<dim3(NCHUNK, B_), TPB1, SMEM1>>>(h, u, w_h, b_h, w_u, b_u, w_hu, b_hu, out);
    bidaf_k2<<<B_, 256>>>();
    bidaf_k3<<<dim3(NCHUNK, B_), 256>>>(h, out);
}

// round 7
// speedup vs baseline: 1.6268x; 1.6268x over previous
#include <cuda_runtime.h>

#define B_ 64
#define T_ 800
#define J_ 50
#define D_ 200

constexpr int TPB1 = 256;
constexpr int NW   = 8;          // warps per block
constexpr int TT   = 4;          // t-rows per warp (phase B / softmax)
constexpr int TP   = 8;          // t-rows per warp pair (c2q)
constexpr int TBLK = NW * TT;    // 32 t-rows per block
constexpr int UPITCH4 = 51;      // float4 per u row (204 words; conflict-free)
constexpr int D4 = D_ / 4;       // 50
constexpr int KH = 25;           // d4-chunks per half (c2q split)
constexpr int NCHUNK = 25;       // = T_/TBLK
constexpr int ATP = 12;          // a_T pitch (floats): 48B, 16B-aligned rows

// scratch (no cudaMalloc allowed)
__device__ float2 g_cm[B_ * NCHUNK];            // (chunk max, chunk expsum)
__device__ float  g_part[B_ * NCHUNK * D_];     // unnormalized q2c partials
__device__ __align__(16) float g_q2c[B_ * D_];  // combined q2c

// ---- packed f32x2 helpers ----
__device__ __forceinline__ void fma2(unsigned long long& d, unsigned long long a, unsigned long long b) {
    asm("fma.rn.f32x2 %0, %1, %2, %0;" : "+l"(d) : "l"(a), "l"(b));
}
__device__ __forceinline__ unsigned long long dup2(float a) {
    unsigned long long r;
    asm("mov.b64 %0, {%1, %1};" : "=l"(r) : "f"(a));
    return r;
}
__device__ __forceinline__ float2 unpack2(unsigned long long v) {
    float2 r; asm("mov.b64 {%0, %1}, %2;" : "=f"(r.x), "=f"(r.y) : "l"(v)); return r;
}
__device__ __forceinline__ float warpSum(float v) {
    #pragma unroll
    for (int o = 16; o > 0; o >>= 1) v += __shfl_xor_sync(0xffffffffu, v, o);
    return v;
}
__device__ __forceinline__ float warpMax(float v) {
    #pragma unroll
    for (int o = 16; o > 0; o >>= 1) v = fmaxf(v, __shfl_xor_sync(0xffffffffu, v, o));
    return v;
}
__device__ __forceinline__ void barPair(int p) {
    asm volatile("bar.sync %0, 64;" :: "r"(p + 1) : "memory");
}

// =====================================================================
// K1: per (b, 32 t-rows): s row (warp-private, 4 rows), softmax over J,
// c2q pair-split by d-half with transposed-a broadcasts, out[:,0:600],
// plus chunk-local q2c partial.
// smem: u_s 40800 + hw_s 25600 + su 208 + m/es 256 = 66.9KB -> 3 CTAs/SM
// =====================================================================
__global__ __launch_bounds__(TPB1, 3) void bidaf_k1(
    const float* __restrict__ h, const float* __restrict__ u,
    const float* __restrict__ w_h, const float* __restrict__ b_h,
    const float* __restrict__ w_u, const float* __restrict__ b_u,
    const float* __restrict__ w_hu, const float* __restrict__ b_hu,
    float* __restrict__ out)
{
    extern __shared__ char smem_raw[];
    float* u_s  = (float*)smem_raw;                  // 50*204
    float* hw_s = u_s + J_ * UPITCH4 * 4;            // 32*200
    float* su_s = hw_s + TBLK * D_;                  // 50 (+2 pad)
    float* m_s  = su_s + J_ + 2;                     // 32
    float* es_s = m_s + TBLK;                        // 32

    const int b    = blockIdx.y;
    const int c    = blockIdx.x;
    const int t0   = c * TBLK;
    const int tid  = threadIdx.x;
    const int warp = tid >> 5, lane = tid & 31;
    const int pair = warp >> 1, half = warp & 1;

    const float4* u4g = (const float4*)u;
    const float4* h4g = (const float4*)h;
    float4* us4 = (float4*)u_s;

    // ---- load u[b] tile into smem ----
    for (int idx = tid; idx < J_ * UPITCH4; idx += TPB1) {
        int j = idx / UPITCH4, k = idx - j * UPITCH4;
        if (k < D4) us4[j * UPITCH4 + k] = u4g[(b * J_ + j) * D4 + k];
    }
    const float bias = b_h[0] + b_u[0] + b_hu[0];
    __syncthreads();

    // ---- su_s[j] = dot(u_j, w_u) + bias ----
    const float4* wu4 = (const float4*)w_u;
    for (int j = warp; j < J_; j += NW) {
        float acc = 0.f;
        for (int k = lane; k < D4; k += 32) {
            float4 a = us4[j * UPITCH4 + k], w = wu4[k];
            acc += a.x * w.x + a.y * w.y + a.z * w.z + a.w * w.w;
        }
        acc = warpSum(acc);
        if (lane == 0) su_s[j] = acc + bias;
    }
    __syncthreads();

    // ---- phase A: hw = h * w_hu (to smem), sh = dot(h, w_h) ----
    const float4* whu4 = (const float4*)w_hu;
    const float4* wh4  = (const float4*)w_h;
    float4* hw4 = (float4*)hw_s + warp * (TT * D4);
    const int tw = t0 + warp * TT;
    float sh[TT];
    #pragma unroll
    for (int tt = 0; tt < TT; tt++) {
        long rb = (long)(b * T_ + tw + tt) * D4;
        float4 a = h4g[rb + lane];
        float4 w1 = whu4[lane];
        hw4[tt * D4 + lane] =
            make_float4(a.x * w1.x, a.y * w1.y, a.z * w1.z, a.w * w1.w);
        float4 w2 = wh4[lane];
        float p = a.x * w2.x + a.y * w2.y + a.z * w2.z + a.w * w2.w;
        if (lane < D4 - 32) {
            float4 a2 = h4g[rb + 32 + lane];
            float4 w1b = whu4[32 + lane];
            hw4[tt * D4 + 32 + lane] =
                make_float4(a2.x * w1b.x, a2.y * w1b.y, a2.z * w1b.z, a2.w * w1b.w);
            float4 w2b = wh4[32 + lane];
            p += a2.x * w2b.x + a2.y * w2b.y + a2.z * w2b.z + a2.w * w2b.w;
        }
        sh[tt] = warpSum(p);
    }
    __syncwarp();

    // ---- phase B (round-5 style): s[t,j] over full d, own 4 rows ----
    const bool jv = (lane < J_ - 32);
    unsigned long long acc[TT][2];
    #pragma unroll
    for (int tt = 0; tt < TT; tt++) { acc[tt][0] = 0ull; acc[tt][1] = 0ull; }

    const ulonglong2* usU = (const ulonglong2*)u_s;
    const ulonglong2* hwW = (const ulonglong2*)hw_s + warp * (TT * D4);
    const int j0 = lane, j1 = lane + 32;
    const ulonglong2* uj0 = usU + j0 * UPITCH4;
    const ulonglong2* uj1 = usU + j1 * UPITCH4;

    #pragma unroll 2
    for (int k = 0; k < D4; k++) {
        ulonglong2 U0 = uj0[k];
        ulonglong2 U1; U1.x = 0ull; U1.y = 0ull;
        if (jv) U1 = uj1[k];
        #pragma unroll
        for (int tt = 0; tt < TT; tt++) {
            ulonglong2 Hb = hwW[tt * D4 + k];  // broadcast
            fma2(acc[tt][0], U0.x, Hb.x);
            fma2(acc[tt][0], U0.y, Hb.y);
            fma2(acc[tt][1], U1.x, Hb.x);
            fma2(acc[tt][1], U1.y, Hb.y);
        }
    }
    // partner may still be reading its hw rows; a_T overlays pair region
    barPair(pair);

    // ---- softmax (own 4 rows); transposed a_T[j*12 + r] overlay in pair hw ----
    float* aT = hw_s + pair * (TP * D_);   // 52*12 floats < pair region
    const float su0 = su_s[j0];
    const float su1 = jv ? su_s[j1] : -1e30f;
    #pragma unroll
    for (int tt = 0; tt < TT; tt++) {
        const int r = half * TT + tt;
        float2 p0 = unpack2(acc[tt][0]);
        float2 p1 = unpack2(acc[tt][1]);
        float s0 = p0.x + p0.y + sh[tt] + su0;
        float s1 = p1.x + p1.y + sh[tt] + su1;
        float mx = warpMax(fmaxf(s0, s1));
        float e0 = __expf(s0 - mx);
        float e1 = __expf(s1 - mx);
        float sm = warpSum(e0 + e1);
        float inv = 1.f / sm;
        aT[j0 * ATP + r] = e0 * inv;
        if (jv) aT[j1 * ATP + r] = e1 * inv;
        if (lane == 0) m_s[pair * TP + r] = mx;
    }
    barPair(pair);

    // ---- c2q pair-split: this warp's d-half, all 8 pair rows ----
    unsigned long long cacc[TP][2];
    #pragma unroll
    for (int r = 0; r < TP; r++) { cacc[r][0] = 0ull; cacc[r][1] = 0ull; }

    const bool kvalid = (lane < KH);
    const int myk = half * KH + lane;            // this lane's d4 chunk
    const ulonglong2* ukp = usU + (kvalid ? myk : 0);
    const float4* aT4 = (const float4*)aT;

    #pragma unroll 2
    for (int j = 0; j < J_; j++) {
        ulonglong2 Ua; Ua.x = 0ull; Ua.y = 0ull;
        if (kvalid) Ua = ukp[j * UPITCH4];
        float4 b0 = aT4[j * (ATP / 4)];          // a rows 0..3 (broadcast)
        float4 b1 = aT4[j * (ATP / 4) + 1];      // a rows 4..7 (broadcast)
        unsigned long long a0 = dup2(b0.x), a1 = dup2(b0.y),
                           a2 = dup2(b0.z), a3 = dup2(b0.w);
        fma2(cacc[0][0], a0, Ua.x); fma2(cacc[0][1], a0, Ua.y);
        fma2(cacc[1][0], a1, Ua.x); fma2(cacc[1][1], a1, Ua.y);
        fma2(cacc[2][0], a2, Ua.x); fma2(cacc[2][1], a2, Ua.y);
        fma2(cacc[3][0], a3, Ua.x); fma2(cacc[3][1], a3, Ua.y);
        unsigned long long a4 = dup2(b1.x), a5 = dup2(b1.y),
                           a6 = dup2(b1.z), a7 = dup2(b1.w);
        fma2(cacc[4][0], a4, Ua.x); fma2(cacc[4][1], a4, Ua.y);
        fma2(cacc[5][0], a5, Ua.x); fma2(cacc[5][1], a5, Ua.y);
        fma2(cacc[6][0], a6, Ua.x); fma2(cacc[6][1], a6, Ua.y);
        fma2(cacc[7][0], a7, Ua.x); fma2(cacc[7][1], a7, Ua.y);
    }

    // ---- epilogue: out[b,t, 0:200]=h, [200:400]=c2q, [400:600]=h*c2q ----
    if (kvalid) {
        #pragma unroll
        for (int r = 0; r < TP; r++) {
            int t = t0 + pair * TP + r;
            long rb = (long)(b * T_ + t) * D4;
            float4* o4 = (float4*)out + (long)(b * T_ + t) * (4 * D4);
            float4 ha = h4g[rb + myk];
            float2 ca = unpack2(cacc[r][0]);
            float2 cb = unpack2(cacc[r][1]);
            float4 c0 = make_float4(ca.x, ca.y, cb.x, cb.y);
            __stcs(o4 + myk, ha);
            __stcs(o4 + 50 + myk, c0);
            __stcs(o4 + 100 + myk,
                   make_float4(ha.x * c0.x, ha.y * c0.y, ha.z * c0.z, ha.w * c0.w));
        }
    }

    // ---- chunk-local q2c partial ----
    __syncthreads();
    if (warp == 0) {
        float mv = (lane < TBLK) ? m_s[lane] : -3.0e38f;
        float mc = warpMax(mv);
        float ev = (lane < TBLK) ? __expf(mv - mc) : 0.f;
        float sc = warpSum(ev);
        if (lane < TBLK) es_s[lane] = ev;
        if (lane == 0) g_cm[b * NCHUNK + c] = make_float2(mc, sc);
    }
    __syncthreads();
    if (tid < D_) {
        const float* hp = h + ((long)b * T_ + t0) * D_ + tid;
        float a0 = 0.f, a1 = 0.f, a2 = 0.f, a3 = 0.f;
        #pragma unroll
        for (int t = 0; t < TBLK; t += 4) {
            a0 += es_s[t]     * hp[t * D_];
            a1 += es_s[t + 1] * hp[(t + 1) * D_];
            a2 += es_s[t + 2] * hp[(t + 2) * D_];
            a3 += es_s[t + 3] * hp[(t + 3) * D_];
        }
        g_part[(b * NCHUNK + c) * D_ + tid] = (a0 + a1) + (a2 + a3);
    }
}

// =====================================================================
// K2: per-batch combine of chunk records -> g_q2c[b,:]
// =====================================================================
__global__ __launch_bounds__(256) void bidaf_k2()
{
    __shared__ float ws[32];
    __shared__ float Ss;
    const int b = blockIdx.x, tid = threadIdx.x;
    if (tid < 32) {
        float2 cm = (tid < NCHUNK) ? g_cm[b * NCHUNK + tid] : make_float2(-3.0e38f, 0.f);
        float M = warpMax(cm.x);
        float e = (tid < NCHUNK) ? __expf(cm.x - M) : 0.f;
        float S = warpSum(e * cm.y);
        ws[tid] = e;
        if (tid == 0) Ss = S;
    }
    __syncthreads();
    if (tid < D_) {
        float acc = 0.f;
        #pragma unroll
        for (int c2 = 0; c2 < NCHUNK; c2++)
            acc += ws[c2] * g_part[(b * NCHUNK + c2) * D_ + tid];
        g_q2c[b * D_ + tid] = acc / Ss;
    }
}

// =====================================================================
// K3: flat streaming: out[b,t,600:800] = h[b,t,:] * q2c[b,:]
// one thread per float4; 10000 blocks for max latency hiding
// =====================================================================
__global__ __launch_bounds__(256) void bidaf_k3(const float* __restrict__ h,
                                                float* __restrict__ out)
{
    long idx = (long)blockIdx.x * 256 + threadIdx.x;   // float4 index
    if (idx >= (long)B_ * T_ * D4) return;
    int d4 = (int)(idx % D4);
    long bt = idx / D4;
    int b = (int)(bt / T_);
    float4 hv = __ldg(((const float4*)h) + idx);
    float4 q  = __ldg(((const float4*)g_q2c) + b * D4 + d4);
    __stcs(((float4*)out) + bt * (4 * D4) + 150 + d4,
           make_float4(hv.x * q.x, hv.y * q.y, hv.z * q.z, hv.w * q.w));
}

// =====================================================================
extern "C" void kernel_launch(void* const* d_in, const int* in_sizes, int n_in,
                              void* d_out, int out_size)
{
    const float* h    = (const float*)d_in[0];
    const float* u    = (const float*)d_in[1];
    const float* w_h  = (const float*)d_in[2];
    const float* b_h  = (const float*)d_in[3];
    const float* w_u  = (const float*)d_in[4];
    const float* b_u  = (const float*)d_in[5];
    const float* w_hu = (const float*)d_in[6];
    const float* b_hu = (const float*)d_in[7];
    float* out = (float*)d_out;

    constexpr int SMEM1 = (J_ * UPITCH4 * 4      // u_s
                         + TBLK * D_             // hw_s (a_T overlays)
                         + J_ + 2                // su_s
                         + 2 * TBLK) * 4;        // m_s + es_s
    cudaFuncSetAttribute(bidaf_k1, cudaFuncAttributeMaxDynamicSharedMemorySize, SMEM1);

    bidaf_k1<<<dim3(NCHUNK, B_), TPB1, SMEM1>>>(h, u, w_h, b_h, w_u, b_u, w_hu, b_hu, out);
    bidaf_k2<<<B_, 256>>>();
    int total4 = B_ * T_ * D4;
    bidaf_k3<<<(total4 + 255) / 256, 256>>>(h, out);
}